// round 1
// baseline (speedup 1.0000x reference)
#include <cuda_runtime.h>
#include <math.h>

// Problem constants
#define B_   4
#define T_   2048
#define C_   2048
#define NH   16
#define NKV  4
#define HD_  128
#define QKVD ((NH + 2 * NKV) * HD_)   // 3072
#define QKV_STRIDE QKVD               // row stride in qkv buffer

// ---------------- scratch (device globals; no runtime allocation) ----------
__device__ float g_qkv[(size_t)B_ * T_ * QKVD];     // [B,T,24,128]
__device__ float g_y[(size_t)B_ * T_ * C_];         // [B,T,C] attention output
__device__ float g_cos[T_ * (HD_ / 2)];
__device__ float g_sin[T_ * (HD_ / 2)];

// ---------------- packed f32x2 helpers -------------------------------------
__device__ __forceinline__ unsigned long long pack2(float x, float y) {
    unsigned long long r;
    asm("mov.b64 %0, {%1, %2};" : "=l"(r) : "f"(x), "f"(y));
    return r;
}
__device__ __forceinline__ float2 unpack2(unsigned long long p) {
    float2 f;
    asm("mov.b64 {%0, %1}, %2;" : "=f"(f.x), "=f"(f.y) : "l"(p));
    return f;
}
__device__ __forceinline__ void ffma2(unsigned long long& d,
                                      unsigned long long a,
                                      unsigned long long b) {
    asm("fma.rn.f32x2 %0, %1, %2, %0;" : "+l"(d) : "l"(a), "l"(b));
}

// ---------------- RoPE cos/sin table (double precision to match fp32 ref) --
__global__ void rope_table_kernel() {
    int idx = blockIdx.x * blockDim.x + threadIdx.x;
    if (idx >= T_ * (HD_ / 2)) return;
    int t = idx / (HD_ / 2);
    int i = idx % (HD_ / 2);
    double inv = exp(-((double)i / 64.0) * log(10000.0));
    double ang = (double)t * inv;
    g_cos[idx] = (float)cos(ang);
    g_sin[idx] = (float)sin(ang);
}

// ---------------- RoPE apply to q (heads 0..15) and k (heads 16..19) -------
__global__ void rope_apply_kernel() {
    int idx = blockIdx.x * blockDim.x + threadIdx.x;
    const int total = B_ * T_ * (NH + NKV) * (HD_ / 2);
    if (idx >= total) return;
    int i = idx & 63;
    int h = (idx >> 6) % (NH + NKV);
    int t = ((idx >> 6) / (NH + NKV)) % T_;
    int b = idx / (64 * (NH + NKV) * T_);
    size_t base = (((size_t)b * T_ + t) * 24 + h) * HD_ + 2 * i;
    float2 x01 = *(float2*)&g_qkv[base];
    float c = g_cos[t * 64 + i];
    float s = g_sin[t * 64 + i];
    float2 o;
    o.x = x01.x * c - x01.y * s;
    o.y = x01.x * s + x01.y * c;
    *(float2*)&g_qkv[base] = o;
}

// ---------------- SGEMM (NT): C[m][n] = sum_k A[m][k] * B[n][k] ------------
// A: [M,K] row-major, B: [N,K] row-major. 128x128x16 tiles, 8x8 microtile,
// packed f32x2 FMA inner loop. M,N,K multiples of 128/128/16. 256 threads.
__global__ __launch_bounds__(256) void sgemm_nt(const float* __restrict__ A,
                                                const float* __restrict__ Bm,
                                                float* __restrict__ Cm,
                                                int M, int N, int K) {
    const int BM = 128, BN = 128, BK = 16;
    __shared__ float As[BK][BM];
    __shared__ float Bs[BK][BN];
    const int tid = threadIdx.x;
    const int tx = tid & 15;
    const int ty = tid >> 4;
    const size_t bm = (size_t)blockIdx.y * BM;
    const size_t bn = (size_t)blockIdx.x * BN;

    unsigned long long acc[8][4];
#pragma unroll
    for (int i = 0; i < 8; i++)
#pragma unroll
        for (int j = 0; j < 4; j++) acc[i][j] = 0ull;

    const float* Ag = A + bm * K;
    const float* Bg = Bm + bn * K;

    for (int k0 = 0; k0 < K; k0 += BK) {
#pragma unroll
        for (int s = 0; s < 2; s++) {
            int it = tid + s * 256;      // 0..511
            int row = it >> 2;           // 0..127
            int c4 = (it & 3) << 2;      // 0,4,8,12
            float4 a = *(const float4*)(Ag + (size_t)row * K + k0 + c4);
            As[c4 + 0][row] = a.x;
            As[c4 + 1][row] = a.y;
            As[c4 + 2][row] = a.z;
            As[c4 + 3][row] = a.w;
            float4 b = *(const float4*)(Bg + (size_t)row * K + k0 + c4);
            Bs[c4 + 0][row] = b.x;
            Bs[c4 + 1][row] = b.y;
            Bs[c4 + 2][row] = b.z;
            Bs[c4 + 3][row] = b.w;
        }
        __syncthreads();
#pragma unroll
        for (int k = 0; k < BK; k++) {
            float4 a0 = *(const float4*)&As[k][8 * ty];
            float4 a1 = *(const float4*)&As[k][8 * ty + 4];
            float4 b0 = *(const float4*)&Bs[k][8 * tx];
            float4 b1 = *(const float4*)&Bs[k][8 * tx + 4];
            unsigned long long bp[4];
            bp[0] = pack2(b0.x, b0.y);
            bp[1] = pack2(b0.z, b0.w);
            bp[2] = pack2(b1.x, b1.y);
            bp[3] = pack2(b1.z, b1.w);
            float av[8] = {a0.x, a0.y, a0.z, a0.w, a1.x, a1.y, a1.z, a1.w};
#pragma unroll
            for (int i = 0; i < 8; i++) {
                unsigned long long ap = pack2(av[i], av[i]);
#pragma unroll
                for (int j = 0; j < 4; j++) ffma2(acc[i][j], ap, bp[j]);
            }
        }
        __syncthreads();
    }

#pragma unroll
    for (int i = 0; i < 8; i++) {
        float* c = Cm + (bm + 8 * ty + i) * (size_t)N + bn + 8 * tx;
        float2 p0 = unpack2(acc[i][0]);
        float2 p1 = unpack2(acc[i][1]);
        float2 p2 = unpack2(acc[i][2]);
        float2 p3 = unpack2(acc[i][3]);
        float4 o0 = make_float4(p0.x, p0.y, p1.x, p1.y);
        float4 o1 = make_float4(p2.x, p2.y, p3.x, p3.y);
        *(float4*)c = o0;
        *(float4*)(c + 4) = o1;
    }
}

// ---------------- Flash attention (causal, GQA) ----------------------------
// Grid: (T/64, NH, B), 256 threads (16x16). Q tile 64, K tile 64, 4x4 micro.
// Qs/Ks stored transposed [HD][64] for vectorized conflict-free reads.
__global__ __launch_bounds__(256) void flash_kernel() {
    extern __shared__ float sm[];
    float* Qs = sm;                   // [128][64]
    float* Ks = sm + 128 * 64;        // [128][64]
    float* Vs = Ks + 128 * 64;        // [64][128]
    float* Pt = Vs + 64 * 128;        // [64][65] (padded)

    const int tid = threadIdx.x;
    const int tx = tid & 15;
    const int ty = tid >> 4;
    const int qt = (gridDim.x - 1) - blockIdx.x;   // longest blocks first
    const int h = blockIdx.y;
    const int b = blockIdx.z;
    const int kvh = h >> 2;  // n_rep = 4

    const float* qptr = g_qkv + (((size_t)b * T_ + (size_t)qt * 64) * 24 + h) * HD_;
    const float* kbase = g_qkv + ((size_t)b * T_ * 24 + (NH + kvh)) * HD_;
    const float* vbase = g_qkv + ((size_t)b * T_ * 24 + (NH + NKV + kvh)) * HD_;

    // load Q tile transposed: Qs[c][r], c in 0..127, r in 0..63
#pragma unroll
    for (int s = 0; s < 8; s++) {
        int it = tid + s * 256;                      // 0..2047
        int c4 = (it & 3) + ((it >> 8) << 2);        // 0..31
        int r = (it >> 2) & 63;
        float4 v = *(const float4*)(qptr + (size_t)r * QKV_STRIDE + c4 * 4);
        Qs[(4 * c4 + 0) * 64 + r] = v.x;
        Qs[(4 * c4 + 1) * 64 + r] = v.y;
        Qs[(4 * c4 + 2) * 64 + r] = v.z;
        Qs[(4 * c4 + 3) * 64 + r] = v.w;
    }

    float m_i[4], l_i[4], O[4][8];
#pragma unroll
    for (int i = 0; i < 4; i++) {
        m_i[i] = -INFINITY;
        l_i[i] = 0.0f;
#pragma unroll
        for (int c = 0; c < 8; c++) O[i][c] = 0.0f;
    }

    const float scale = 0.08838834764831843f;  // 1/sqrt(128)

    for (int kt = 0; kt <= qt; kt++) {
        __syncthreads();  // previous PV done (and Q load on first iter)
        const size_t kv0 = (size_t)kt * 64;
        // K tile transposed
#pragma unroll
        for (int s = 0; s < 8; s++) {
            int it = tid + s * 256;
            int c4 = (it & 3) + ((it >> 8) << 2);
            int r = (it >> 2) & 63;
            float4 v = *(const float4*)(kbase + (kv0 + r) * QKV_STRIDE + c4 * 4);
            Ks[(4 * c4 + 0) * 64 + r] = v.x;
            Ks[(4 * c4 + 1) * 64 + r] = v.y;
            Ks[(4 * c4 + 2) * 64 + r] = v.z;
            Ks[(4 * c4 + 3) * 64 + r] = v.w;
        }
        // V tile natural [64][128]
#pragma unroll
        for (int s = 0; s < 8; s++) {
            int it = tid + s * 256;
            int r = it >> 5;
            int c4 = it & 31;
            float4 v = *(const float4*)(vbase + (kv0 + r) * QKV_STRIDE + c4 * 4);
            *(float4*)&Vs[r * 128 + c4 * 4] = v;
        }
        __syncthreads();

        // S = Q K^T  (4x4 per thread)
        float s_[4][4] = {{0, 0, 0, 0}, {0, 0, 0, 0}, {0, 0, 0, 0}, {0, 0, 0, 0}};
#pragma unroll 8
        for (int k = 0; k < HD_; k++) {
            float4 a = *(const float4*)&Qs[k * 64 + 4 * ty];
            float4 bq = *(const float4*)&Ks[k * 64 + 4 * tx];
            float av[4] = {a.x, a.y, a.z, a.w};
            float bv[4] = {bq.x, bq.y, bq.z, bq.w};
#pragma unroll
            for (int i = 0; i < 4; i++)
#pragma unroll
                for (int j = 0; j < 4; j++) s_[i][j] = fmaf(av[i], bv[j], s_[i][j]);
        }

        // scale + causal mask
        if (kt == qt) {
#pragma unroll
            for (int i = 0; i < 4; i++) {
                int qi = 4 * ty + i;
#pragma unroll
                for (int j = 0; j < 4; j++) {
                    int kj = 4 * tx + j;
                    s_[i][j] = (kj <= qi) ? s_[i][j] * scale : -INFINITY;
                }
            }
        } else {
#pragma unroll
            for (int i = 0; i < 4; i++)
#pragma unroll
                for (int j = 0; j < 4; j++) s_[i][j] *= scale;
        }

        // online softmax update (row stats over 16 tx lanes)
#pragma unroll
        for (int i = 0; i < 4; i++) {
            float rm = fmaxf(fmaxf(s_[i][0], s_[i][1]), fmaxf(s_[i][2], s_[i][3]));
#pragma unroll
            for (int off = 8; off >= 1; off >>= 1)
                rm = fmaxf(rm, __shfl_xor_sync(0xffffffffu, rm, off));
            float mn = fmaxf(m_i[i], rm);
            float corr = __expf(m_i[i] - mn);
            m_i[i] = mn;
            float rs = 0.0f;
#pragma unroll
            for (int j = 0; j < 4; j++) {
                float p = __expf(s_[i][j] - mn);
                s_[i][j] = p;
                rs += p;
            }
#pragma unroll
            for (int off = 8; off >= 1; off >>= 1)
                rs += __shfl_xor_sync(0xffffffffu, rs, off);
            l_i[i] = l_i[i] * corr + rs;
#pragma unroll
            for (int c = 0; c < 8; c++) O[i][c] *= corr;
        }

        // write P transposed Pt[k][r] (pitch 65)
#pragma unroll
        for (int j = 0; j < 4; j++)
#pragma unroll
            for (int i = 0; i < 4; i++)
                Pt[(4 * tx + j) * 65 + 4 * ty + i] = s_[i][j];
        __syncthreads();

        // O += P V
#pragma unroll 4
        for (int k = 0; k < 64; k++) {
            float4 v0 = *(const float4*)&Vs[k * 128 + 8 * tx];
            float4 v1 = *(const float4*)&Vs[k * 128 + 8 * tx + 4];
            float p0 = Pt[k * 65 + 4 * ty + 0];
            float p1 = Pt[k * 65 + 4 * ty + 1];
            float p2 = Pt[k * 65 + 4 * ty + 2];
            float p3 = Pt[k * 65 + 4 * ty + 3];
            float pv[4] = {p0, p1, p2, p3};
#pragma unroll
            for (int i = 0; i < 4; i++) {
                O[i][0] = fmaf(pv[i], v0.x, O[i][0]);
                O[i][1] = fmaf(pv[i], v0.y, O[i][1]);
                O[i][2] = fmaf(pv[i], v0.z, O[i][2]);
                O[i][3] = fmaf(pv[i], v0.w, O[i][3]);
                O[i][4] = fmaf(pv[i], v1.x, O[i][4]);
                O[i][5] = fmaf(pv[i], v1.y, O[i][5]);
                O[i][6] = fmaf(pv[i], v1.z, O[i][6]);
                O[i][7] = fmaf(pv[i], v1.w, O[i][7]);
            }
        }
    }

    // epilogue: O / l -> y[b][t][h*128 + c]
#pragma unroll
    for (int i = 0; i < 4; i++) {
        float inv = 1.0f / l_i[i];
        size_t tq = (size_t)qt * 64 + 4 * ty + i;
        float* yo = g_y + ((size_t)b * T_ + tq) * C_ + h * HD_ + 8 * tx;
        float4 o0 = make_float4(O[i][0] * inv, O[i][1] * inv, O[i][2] * inv, O[i][3] * inv);
        float4 o1 = make_float4(O[i][4] * inv, O[i][5] * inv, O[i][6] * inv, O[i][7] * inv);
        *(float4*)yo = o0;
        *(float4*)(yo + 4) = o1;
    }
}

// ---------------- driver ----------------------------------------------------
extern "C" void kernel_launch(void* const* d_in, const int* in_sizes, int n_in,
                              void* d_out, int out_size) {
    const float* x = nullptr;
    const float* w_attn = nullptr;
    const float* w_proj = nullptr;
    for (int i = 0; i < n_in; i++) {
        if (in_sizes[i] == B_ * T_ * C_) x = (const float*)d_in[i];
        else if (in_sizes[i] == QKVD * C_) w_attn = (const float*)d_in[i];
        else if (in_sizes[i] == C_ * C_) w_proj = (const float*)d_in[i];
    }
    float* out = (float*)d_out;

    float* qkv;
    float* y;
    cudaGetSymbolAddress((void**)&qkv, g_qkv);
    cudaGetSymbolAddress((void**)&y, g_y);

    // flash needs ~115 KB dynamic smem
    const int flash_smem = (128 * 64 + 128 * 64 + 64 * 128 + 64 * 65) * 4;
    cudaFuncSetAttribute(flash_kernel, cudaFuncAttributeMaxDynamicSharedMemorySize,
                         flash_smem);

    // 1. RoPE table
    rope_table_kernel<<<(T_ * 64 + 255) / 256, 256>>>();

    // 2. qkv = x @ w_attn^T   (M=8192, N=3072, K=2048)
    {
        dim3 grid(QKVD / 128, (B_ * T_) / 128);
        sgemm_nt<<<grid, 256>>>(x, w_attn, qkv, B_ * T_, QKVD, C_);
    }

    // 3. RoPE apply to q,k
    {
        int total = B_ * T_ * (NH + NKV) * 64;
        rope_apply_kernel<<<(total + 255) / 256, 256>>>();
    }

    // 4. flash attention -> y
    {
        dim3 grid(T_ / 64, NH, B_);
        flash_kernel<<<grid, 256, flash_smem>>>();
    }

    // 5. out = y @ w_proj^T   (M=8192, N=2048, K=2048)
    {
        dim3 grid(C_ / 128, (B_ * T_) / 128);
        sgemm_nt<<<grid, 256>>>(y, w_proj, out, B_ * T_, C_, C_);
    }
}

// round 3
// speedup vs baseline: 1.5565x; 1.5565x over previous
#include <cuda_runtime.h>
#include <cuda_bf16.h>
#include <math.h>
#include <stdint.h>

// Problem constants
#define B_   4
#define T_   2048
#define C_   2048
#define NH   16
#define NKV  4
#define HD_  128
#define QKVD ((NH + 2 * NKV) * HD_)   // 3072
#define QKV_STRIDE QKVD

// ---------------- scratch (device globals; no runtime allocation) ----------
__device__ float g_qkv[(size_t)B_ * T_ * QKVD];     // [B,T,24,128]
__device__ float g_y[(size_t)B_ * T_ * C_];         // [B,T,C] attention output
__device__ float g_cos[T_ * (HD_ / 2)];
__device__ float g_sin[T_ * (HD_ / 2)];
// bf16 hi/lo split operands for tensor-core GEMMs
__device__ __nv_bfloat16 g_xh[(size_t)B_ * T_ * C_];
__device__ __nv_bfloat16 g_xl[(size_t)B_ * T_ * C_];
__device__ __nv_bfloat16 g_yh[(size_t)B_ * T_ * C_];
__device__ __nv_bfloat16 g_yl[(size_t)B_ * T_ * C_];
__device__ __nv_bfloat16 g_wah[(size_t)QKVD * C_];
__device__ __nv_bfloat16 g_wal[(size_t)QKVD * C_];
__device__ __nv_bfloat16 g_wph[(size_t)C_ * C_];
__device__ __nv_bfloat16 g_wpl[(size_t)C_ * C_];

// ---------------- small PTX helpers ----------------------------------------
__device__ __forceinline__ uint32_t smem_u32(const void* p) {
    uint32_t a;
    asm("{ .reg .u64 t; cvta.to.shared.u64 t, %1; cvt.u32.u64 %0, t; }"
        : "=r"(a) : "l"(p));
    return a;
}
__device__ __forceinline__ void cpa16(uint32_t d, const void* g) {
    asm volatile("cp.async.cg.shared.global [%0], [%1], 16;" :: "r"(d), "l"(g));
}
__device__ __forceinline__ void cpa_commit() {
    asm volatile("cp.async.commit_group;" ::: "memory");
}
template <int N>
__device__ __forceinline__ void cpa_wait() {
    asm volatile("cp.async.wait_group %0;" :: "n"(N) : "memory");
}
__device__ __forceinline__ void ldsm_x4(uint32_t& r0, uint32_t& r1,
                                        uint32_t& r2, uint32_t& r3, uint32_t a) {
    asm volatile("ldmatrix.sync.aligned.m8n8.x4.shared.b16 {%0,%1,%2,%3}, [%4];"
                 : "=r"(r0), "=r"(r1), "=r"(r2), "=r"(r3) : "r"(a));
}
__device__ __forceinline__ void ldsm_x2(uint32_t& r0, uint32_t& r1, uint32_t a) {
    asm volatile("ldmatrix.sync.aligned.m8n8.x2.shared.b16 {%0,%1}, [%2];"
                 : "=r"(r0), "=r"(r1) : "r"(a));
}
__device__ __forceinline__ void mma_bf16(float* c, const uint32_t* a,
                                         const uint32_t* b) {
    asm volatile(
        "mma.sync.aligned.m16n8k16.row.col.f32.bf16.bf16.f32 "
        "{%0,%1,%2,%3},{%4,%5,%6,%7},{%8,%9},{%0,%1,%2,%3};"
        : "+f"(c[0]), "+f"(c[1]), "+f"(c[2]), "+f"(c[3])
        : "r"(a[0]), "r"(a[1]), "r"(a[2]), "r"(a[3]), "r"(b[0]), "r"(b[1]));
}

// ---------------- fp32 -> bf16 hi/lo split ---------------------------------
__global__ void split_kernel(const float* __restrict__ in,
                             __nv_bfloat16* __restrict__ hi,
                             __nv_bfloat16* __restrict__ lo, int n4) {
    int i = blockIdx.x * blockDim.x + threadIdx.x;
    if (i >= n4) return;
    float4 v = ((const float4*)in)[i];
    float vv[4] = {v.x, v.y, v.z, v.w};
    __nv_bfloat16 h[4], l[4];
#pragma unroll
    for (int j = 0; j < 4; j++) {
        h[j] = __float2bfloat16_rn(vv[j]);
        l[j] = __float2bfloat16_rn(vv[j] - __bfloat162float(h[j]));
    }
    ((__nv_bfloat162*)hi)[2 * i]     = __halves2bfloat162(h[0], h[1]);
    ((__nv_bfloat162*)hi)[2 * i + 1] = __halves2bfloat162(h[2], h[3]);
    ((__nv_bfloat162*)lo)[2 * i]     = __halves2bfloat162(l[0], l[1]);
    ((__nv_bfloat162*)lo)[2 * i + 1] = __halves2bfloat162(l[2], l[3]);
}

// ---------------- RoPE ------------------------------------------------------
__global__ void rope_table_kernel() {
    int idx = blockIdx.x * blockDim.x + threadIdx.x;
    if (idx >= T_ * 64) return;
    int t = idx / 64;
    int i = idx % 64;
    double inv = exp(-((double)i / 64.0) * log(10000.0));
    double ang = (double)t * inv;
    g_cos[idx] = (float)cos(ang);
    g_sin[idx] = (float)sin(ang);
}

__global__ void rope_apply_kernel() {
    int idx = blockIdx.x * blockDim.x + threadIdx.x;
    const int total = B_ * T_ * (NH + NKV) * 64;
    if (idx >= total) return;
    int i = idx & 63;
    int h = (idx >> 6) % (NH + NKV);
    int t = ((idx >> 6) / (NH + NKV)) % T_;
    int b = idx / (64 * (NH + NKV) * T_);
    size_t base = (((size_t)b * T_ + t) * 24 + h) * HD_ + 2 * i;
    float2 x01 = *(float2*)&g_qkv[base];
    float c = g_cos[t * 64 + i];
    float s = g_sin[t * 64 + i];
    float2 o;
    o.x = x01.x * c - x01.y * s;
    o.y = x01.x * s + x01.y * c;
    *(float2*)&g_qkv[base] = o;
}

// ---------------- mma.sync bf16x3 GEMM (NT) ---------------------------------
// C[m][n] = sum_k A[m][k]*B[n][k]; A/B as bf16 hi+lo pairs, fp32 out.
// CTA 128x128, BK=32, 8 warps (2x4), warp tile 64x32, m16n8k16 fragments.
#define GPITCH 40                       // bf16 elems per smem row (80 B)
#define GTILE  (128 * GPITCH)           // bf16 elems per operand tile
#define GSTAGE (4 * GTILE)              // Ah, Al, Bh, Bl

__global__ __launch_bounds__(256) void gemm_mma(
    const __nv_bfloat16* __restrict__ Ah, const __nv_bfloat16* __restrict__ Al,
    const __nv_bfloat16* __restrict__ Bh, const __nv_bfloat16* __restrict__ Bl,
    float* __restrict__ Cm, int M, int N, int K) {
    extern __shared__ __nv_bfloat16 smg[];   // 2 stages x GSTAGE
    const int tid = threadIdx.x;
    const int lane = tid & 31;
    const int w = tid >> 5;
    const int wm = w & 1;        // 0..1 -> 64-row half
    const int wn = w >> 1;       // 0..3 -> 32-col quarter
    const size_t bm = (size_t)blockIdx.y * 128;
    const size_t bn = (size_t)blockIdx.x * 128;

    const uint32_t sbase = smem_u32(smg);

    float acc[4][4][4];
#pragma unroll
    for (int i = 0; i < 4; i++)
#pragma unroll
        for (int j = 0; j < 4; j++)
#pragma unroll
            for (int q = 0; q < 4; q++) acc[i][j][q] = 0.0f;

    const int NC = K >> 5;   // K chunks of 32

    // stage loader: 2048 16B chunks, 8 per thread
    auto load_stage = [&](int chunk) {
        uint32_t st = sbase + (uint32_t)(chunk & 1) * (GSTAGE * 2);
        const int k0 = chunk << 5;
#pragma unroll
        for (int s = 0; s < 8; s++) {
            int idx = s * 256 + tid;          // 0..2047
            int tile = idx >> 9;              // 0..3 (Ah, Al, Bh, Bl)
            int row = (idx >> 2) & 127;
            int ch = idx & 3;                 // 16B chunk within 64B row
            uint32_t dst = st + (uint32_t)(tile * GTILE + row * GPITCH + ch * 8) * 2;
            const __nv_bfloat16* src;
            if (tile == 0)      src = Ah + (bm + row) * (size_t)K + k0 + ch * 8;
            else if (tile == 1) src = Al + (bm + row) * (size_t)K + k0 + ch * 8;
            else if (tile == 2) src = Bh + (bn + row) * (size_t)K + k0 + ch * 8;
            else                src = Bl + (bn + row) * (size_t)K + k0 + ch * 8;
            cpa16(dst, src);
        }
        cpa_commit();
    };

    load_stage(0);

    for (int c = 0; c < NC; c++) {
        if (c + 1 < NC) {
            load_stage(c + 1);
            cpa_wait<1>();
        } else {
            cpa_wait<0>();
        }
        __syncthreads();

        uint32_t st = sbase + (uint32_t)(c & 1) * (GSTAGE * 2);
        uint32_t aHh = st;
        uint32_t aLl = st + (uint32_t)GTILE * 2;
        uint32_t bHh = st + (uint32_t)(2 * GTILE) * 2;
        uint32_t bLl = st + (uint32_t)(3 * GTILE) * 2;

#pragma unroll
        for (int ks = 0; ks < 2; ks++) {   // two k16 steps
            const int k0 = ks * 16;
            // A fragments (hi & lo), 4 m-tiles
            uint32_t ah[4][4], al[4][4];
            {
                int mrow = wm * 64 + (lane & 7) + ((lane >> 3) & 1) * 8;
                int kcol = k0 + (lane >> 4) * 8;
                uint32_t off = (uint32_t)(mrow * GPITCH + kcol) * 2;
#pragma unroll
                for (int mi = 0; mi < 4; mi++) {
                    uint32_t ao = off + (uint32_t)(mi * 16 * GPITCH) * 2;
                    ldsm_x4(ah[mi][0], ah[mi][1], ah[mi][2], ah[mi][3], aHh + ao);
                    ldsm_x4(al[mi][0], al[mi][1], al[mi][2], al[mi][3], aLl + ao);
                }
            }
            // B fragments (hi & lo), 4 n-tiles
            uint32_t bh[4][2], bl[4][2];
            {
                int nrow = wn * 32 + (lane & 7);
                int kcol = k0 + ((lane >> 3) & 1) * 8;
                uint32_t off = (uint32_t)(nrow * GPITCH + kcol) * 2;
#pragma unroll
                for (int ni = 0; ni < 4; ni++) {
                    uint32_t bo = off + (uint32_t)(ni * 8 * GPITCH) * 2;
                    ldsm_x2(bh[ni][0], bh[ni][1], bHh + bo);
                    ldsm_x2(bl[ni][0], bl[ni][1], bLl + bo);
                }
            }
#pragma unroll
            for (int mi = 0; mi < 4; mi++)
#pragma unroll
                for (int ni = 0; ni < 4; ni++) {
                    mma_bf16(acc[mi][ni], ah[mi], bh[ni]);
                    mma_bf16(acc[mi][ni], ah[mi], bl[ni]);
                    mma_bf16(acc[mi][ni], al[mi], bh[ni]);
                }
        }
        __syncthreads();
    }

    // epilogue: c-frag rows = lane>>2 (+8), cols = 2*(lane&3)
#pragma unroll
    for (int mi = 0; mi < 4; mi++) {
        size_t r0 = bm + wm * 64 + mi * 16 + (lane >> 2);
#pragma unroll
        for (int ni = 0; ni < 4; ni++) {
            size_t col = bn + wn * 32 + ni * 8 + 2 * (lane & 3);
            float2 v0 = make_float2(acc[mi][ni][0], acc[mi][ni][1]);
            float2 v1 = make_float2(acc[mi][ni][2], acc[mi][ni][3]);
            *(float2*)(Cm + r0 * (size_t)N + col) = v0;
            *(float2*)(Cm + (r0 + 8) * (size_t)N + col) = v1;
        }
    }
}

// ---------------- Flash attention (causal, GQA) — unchanged -----------------
__global__ __launch_bounds__(256) void flash_kernel() {
    extern __shared__ float sm[];
    float* Qs = sm;                   // [128][64]
    float* Ks = sm + 128 * 64;        // [128][64]
    float* Vs = Ks + 128 * 64;        // [64][128]
    float* Pt = Vs + 64 * 128;        // [64][65]

    const int tid = threadIdx.x;
    const int tx = tid & 15;
    const int ty = tid >> 4;
    const int qt = (gridDim.x - 1) - blockIdx.x;
    const int h = blockIdx.y;
    const int b = blockIdx.z;
    const int kvh = h >> 2;

    const float* qptr = g_qkv + (((size_t)b * T_ + (size_t)qt * 64) * 24 + h) * HD_;
    const float* kbase = g_qkv + ((size_t)b * T_ * 24 + (NH + kvh)) * HD_;
    const float* vbase = g_qkv + ((size_t)b * T_ * 24 + (NH + NKV + kvh)) * HD_;

#pragma unroll
    for (int s = 0; s < 8; s++) {
        int it = tid + s * 256;
        int c4 = (it & 3) + ((it >> 8) << 2);
        int r = (it >> 2) & 63;
        float4 v = *(const float4*)(qptr + (size_t)r * QKV_STRIDE + c4 * 4);
        Qs[(4 * c4 + 0) * 64 + r] = v.x;
        Qs[(4 * c4 + 1) * 64 + r] = v.y;
        Qs[(4 * c4 + 2) * 64 + r] = v.z;
        Qs[(4 * c4 + 3) * 64 + r] = v.w;
    }

    float m_i[4], l_i[4], O[4][8];
#pragma unroll
    for (int i = 0; i < 4; i++) {
        m_i[i] = -INFINITY;
        l_i[i] = 0.0f;
#pragma unroll
        for (int c = 0; c < 8; c++) O[i][c] = 0.0f;
    }

    const float scale = 0.08838834764831843f;

    for (int kt = 0; kt <= qt; kt++) {
        __syncthreads();
        const size_t kv0 = (size_t)kt * 64;
#pragma unroll
        for (int s = 0; s < 8; s++) {
            int it = tid + s * 256;
            int c4 = (it & 3) + ((it >> 8) << 2);
            int r = (it >> 2) & 63;
            float4 v = *(const float4*)(kbase + (kv0 + r) * QKV_STRIDE + c4 * 4);
            Ks[(4 * c4 + 0) * 64 + r] = v.x;
            Ks[(4 * c4 + 1) * 64 + r] = v.y;
            Ks[(4 * c4 + 2) * 64 + r] = v.z;
            Ks[(4 * c4 + 3) * 64 + r] = v.w;
        }
#pragma unroll
        for (int s = 0; s < 8; s++) {
            int it = tid + s * 256;
            int r = it >> 5;
            int c4 = it & 31;
            float4 v = *(const float4*)(vbase + (kv0 + r) * QKV_STRIDE + c4 * 4);
            *(float4*)&Vs[r * 128 + c4 * 4] = v;
        }
        __syncthreads();

        float s_[4][4] = {{0, 0, 0, 0}, {0, 0, 0, 0}, {0, 0, 0, 0}, {0, 0, 0, 0}};
#pragma unroll 8
        for (int k = 0; k < HD_; k++) {
            float4 a = *(const float4*)&Qs[k * 64 + 4 * ty];
            float4 bq = *(const float4*)&Ks[k * 64 + 4 * tx];
            float av[4] = {a.x, a.y, a.z, a.w};
            float bv[4] = {bq.x, bq.y, bq.z, bq.w};
#pragma unroll
            for (int i = 0; i < 4; i++)
#pragma unroll
                for (int j = 0; j < 4; j++) s_[i][j] = fmaf(av[i], bv[j], s_[i][j]);
        }

        if (kt == qt) {
#pragma unroll
            for (int i = 0; i < 4; i++) {
                int qi = 4 * ty + i;
#pragma unroll
                for (int j = 0; j < 4; j++) {
                    int kj = 4 * tx + j;
                    s_[i][j] = (kj <= qi) ? s_[i][j] * scale : -INFINITY;
                }
            }
        } else {
#pragma unroll
            for (int i = 0; i < 4; i++)
#pragma unroll
                for (int j = 0; j < 4; j++) s_[i][j] *= scale;
        }

#pragma unroll
        for (int i = 0; i < 4; i++) {
            float rm = fmaxf(fmaxf(s_[i][0], s_[i][1]), fmaxf(s_[i][2], s_[i][3]));
#pragma unroll
            for (int off = 8; off >= 1; off >>= 1)
                rm = fmaxf(rm, __shfl_xor_sync(0xffffffffu, rm, off));
            float mn = fmaxf(m_i[i], rm);
            float corr = __expf(m_i[i] - mn);
            m_i[i] = mn;
            float rs = 0.0f;
#pragma unroll
            for (int j = 0; j < 4; j++) {
                float p = __expf(s_[i][j] - mn);
                s_[i][j] = p;
                rs += p;
            }
#pragma unroll
            for (int off = 8; off >= 1; off >>= 1)
                rs += __shfl_xor_sync(0xffffffffu, rs, off);
            l_i[i] = l_i[i] * corr + rs;
#pragma unroll
            for (int c = 0; c < 8; c++) O[i][c] *= corr;
        }

#pragma unroll
        for (int j = 0; j < 4; j++)
#pragma unroll
            for (int i = 0; i < 4; i++)
                Pt[(4 * tx + j) * 65 + 4 * ty + i] = s_[i][j];
        __syncthreads();

#pragma unroll 4
        for (int k = 0; k < 64; k++) {
            float4 v0 = *(const float4*)&Vs[k * 128 + 8 * tx];
            float4 v1 = *(const float4*)&Vs[k * 128 + 8 * tx + 4];
            float pv[4] = {Pt[k * 65 + 4 * ty + 0], Pt[k * 65 + 4 * ty + 1],
                           Pt[k * 65 + 4 * ty + 2], Pt[k * 65 + 4 * ty + 3]};
#pragma unroll
            for (int i = 0; i < 4; i++) {
                O[i][0] = fmaf(pv[i], v0.x, O[i][0]);
                O[i][1] = fmaf(pv[i], v0.y, O[i][1]);
                O[i][2] = fmaf(pv[i], v0.z, O[i][2]);
                O[i][3] = fmaf(pv[i], v0.w, O[i][3]);
                O[i][4] = fmaf(pv[i], v1.x, O[i][4]);
                O[i][5] = fmaf(pv[i], v1.y, O[i][5]);
                O[i][6] = fmaf(pv[i], v1.z, O[i][6]);
                O[i][7] = fmaf(pv[i], v1.w, O[i][7]);
            }
        }
    }

#pragma unroll
    for (int i = 0; i < 4; i++) {
        float inv = 1.0f / l_i[i];
        size_t tq = (size_t)qt * 64 + 4 * ty + i;
        float* yo = g_y + ((size_t)b * T_ + tq) * C_ + h * HD_ + 8 * tx;
        float4 o0 = make_float4(O[i][0] * inv, O[i][1] * inv, O[i][2] * inv, O[i][3] * inv);
        float4 o1 = make_float4(O[i][4] * inv, O[i][5] * inv, O[i][6] * inv, O[i][7] * inv);
        *(float4*)yo = o0;
        *(float4*)(yo + 4) = o1;
    }
}

// ---------------- driver ----------------------------------------------------
extern "C" void kernel_launch(void* const* d_in, const int* in_sizes, int n_in,
                              void* d_out, int out_size) {
    const float* x = nullptr;
    const float* w_attn = nullptr;
    const float* w_proj = nullptr;
    for (int i = 0; i < n_in; i++) {
        if (in_sizes[i] == B_ * T_ * C_) x = (const float*)d_in[i];
        else if (in_sizes[i] == QKVD * C_) w_attn = (const float*)d_in[i];
        else if (in_sizes[i] == C_ * C_) w_proj = (const float*)d_in[i];
    }
    float* out = (float*)d_out;

    float *qkv, *y;
    __nv_bfloat16 *xh, *xl, *yh, *yl, *wah, *wal, *wph, *wpl;
    cudaGetSymbolAddress((void**)&qkv, g_qkv);
    cudaGetSymbolAddress((void**)&y, g_y);
    cudaGetSymbolAddress((void**)&xh, g_xh);
    cudaGetSymbolAddress((void**)&xl, g_xl);
    cudaGetSymbolAddress((void**)&yh, g_yh);
    cudaGetSymbolAddress((void**)&yl, g_yl);
    cudaGetSymbolAddress((void**)&wah, g_wah);
    cudaGetSymbolAddress((void**)&wal, g_wal);
    cudaGetSymbolAddress((void**)&wph, g_wph);
    cudaGetSymbolAddress((void**)&wpl, g_wpl);

    const int flash_smem = (128 * 64 + 128 * 64 + 64 * 128 + 64 * 65) * 4;
    cudaFuncSetAttribute(flash_kernel, cudaFuncAttributeMaxDynamicSharedMemorySize,
                         flash_smem);
    const int gemm_smem = 2 * GSTAGE * 2;   // 2 stages x GSTAGE bf16 = 81920 B
    cudaFuncSetAttribute(gemm_mma, cudaFuncAttributeMaxDynamicSharedMemorySize,
                         gemm_smem);

    // RoPE table
    rope_table_kernel<<<(T_ * 64 + 255) / 256, 256>>>();

    // splits: x, w_attn, w_proj
    {
        int n4 = (B_ * T_ * C_) / 4;
        split_kernel<<<(n4 + 255) / 256, 256>>>(x, xh, xl, n4);
        n4 = (QKVD * C_) / 4;
        split_kernel<<<(n4 + 255) / 256, 256>>>(w_attn, wah, wal, n4);
        n4 = (C_ * C_) / 4;
        split_kernel<<<(n4 + 255) / 256, 256>>>(w_proj, wph, wpl, n4);
    }

    // GEMM1: qkv = x @ w_attn^T  (M=8192, N=3072, K=2048)
    {
        dim3 grid(QKVD / 128, (B_ * T_) / 128);
        gemm_mma<<<grid, 256, gemm_smem>>>(xh, xl, wah, wal, qkv,
                                           B_ * T_, QKVD, C_);
    }

    // RoPE apply
    {
        int total = B_ * T_ * (NH + NKV) * 64;
        rope_apply_kernel<<<(total + 255) / 256, 256>>>();
    }

    // flash attention -> y
    {
        dim3 grid(T_ / 64, NH, B_);
        flash_kernel<<<grid, 256, flash_smem>>>();
    }

    // split y, then GEMM2: out = y @ w_proj^T  (M=8192, N=2048, K=2048)
    {
        int n4 = (B_ * T_ * C_) / 4;
        split_kernel<<<(n4 + 255) / 256, 256>>>(y, yh, yl, n4);
        dim3 grid(C_ / 128, (B_ * T_) / 128);
        gemm_mma<<<grid, 256, gemm_smem>>>(yh, yl, wph, wpl, out,
                                           B_ * T_, C_, C_);
    }
}

// round 4
// speedup vs baseline: 2.6275x; 1.6881x over previous
#include <cuda_runtime.h>
#include <cuda_bf16.h>
#include <math.h>
#include <stdint.h>

// Problem constants
#define B_   4
#define T_   2048
#define C_   2048
#define NH   16
#define NKV  4
#define HD_  128
#define QKVD ((NH + 2 * NKV) * HD_)   // 3072

// ---------------- scratch (device globals; no runtime allocation) ----------
__device__ float g_qkv[(size_t)B_ * T_ * QKVD];     // [B,T,24,128]
__device__ float g_y[(size_t)B_ * T_ * C_];         // [B,T,C] attention output
__device__ float g_cos[T_ * (HD_ / 2)];
__device__ float g_sin[T_ * (HD_ / 2)];
// bf16 hi/lo splits
__device__ __nv_bfloat16 g_xh[(size_t)B_ * T_ * C_];
__device__ __nv_bfloat16 g_xl[(size_t)B_ * T_ * C_];
__device__ __nv_bfloat16 g_yh[(size_t)B_ * T_ * C_];
__device__ __nv_bfloat16 g_yl[(size_t)B_ * T_ * C_];
__device__ __nv_bfloat16 g_wah[(size_t)QKVD * C_];
__device__ __nv_bfloat16 g_wal[(size_t)QKVD * C_];
__device__ __nv_bfloat16 g_wph[(size_t)C_ * C_];
__device__ __nv_bfloat16 g_wpl[(size_t)C_ * C_];
// head-major bf16 hi/lo q/k/v for flash
__device__ __nv_bfloat16 g_qh[(size_t)B_ * NH * T_ * HD_];
__device__ __nv_bfloat16 g_ql[(size_t)B_ * NH * T_ * HD_];
__device__ __nv_bfloat16 g_kh[(size_t)B_ * NKV * T_ * HD_];
__device__ __nv_bfloat16 g_kl[(size_t)B_ * NKV * T_ * HD_];
__device__ __nv_bfloat16 g_vh[(size_t)B_ * NKV * T_ * HD_];
__device__ __nv_bfloat16 g_vl[(size_t)B_ * NKV * T_ * HD_];

// ---------------- small PTX helpers ----------------------------------------
__device__ __forceinline__ uint32_t smem_u32(const void* p) {
    uint32_t a;
    asm("{ .reg .u64 t; cvta.to.shared.u64 t, %1; cvt.u32.u64 %0, t; }"
        : "=r"(a) : "l"(p));
    return a;
}
__device__ __forceinline__ void cpa16(uint32_t d, const void* g) {
    asm volatile("cp.async.cg.shared.global [%0], [%1], 16;" :: "r"(d), "l"(g));
}
__device__ __forceinline__ void cpa_commit() {
    asm volatile("cp.async.commit_group;" ::: "memory");
}
template <int N>
__device__ __forceinline__ void cpa_wait() {
    asm volatile("cp.async.wait_group %0;" :: "n"(N) : "memory");
}
__device__ __forceinline__ void ldsm_x4(uint32_t& r0, uint32_t& r1,
                                        uint32_t& r2, uint32_t& r3, uint32_t a) {
    asm volatile("ldmatrix.sync.aligned.m8n8.x4.shared.b16 {%0,%1,%2,%3}, [%4];"
                 : "=r"(r0), "=r"(r1), "=r"(r2), "=r"(r3) : "r"(a));
}
__device__ __forceinline__ void ldsm_x2(uint32_t& r0, uint32_t& r1, uint32_t a) {
    asm volatile("ldmatrix.sync.aligned.m8n8.x2.shared.b16 {%0,%1}, [%2];"
                 : "=r"(r0), "=r"(r1) : "r"(a));
}
__device__ __forceinline__ void ldsm_x4_t(uint32_t& r0, uint32_t& r1,
                                          uint32_t& r2, uint32_t& r3, uint32_t a) {
    asm volatile("ldmatrix.sync.aligned.m8n8.x4.trans.shared.b16 {%0,%1,%2,%3}, [%4];"
                 : "=r"(r0), "=r"(r1), "=r"(r2), "=r"(r3) : "r"(a));
}
__device__ __forceinline__ void mma_bf16(float* c, const uint32_t* a,
                                         const uint32_t* b) {
    asm volatile(
        "mma.sync.aligned.m16n8k16.row.col.f32.bf16.bf16.f32 "
        "{%0,%1,%2,%3},{%4,%5,%6,%7},{%8,%9},{%0,%1,%2,%3};"
        : "+f"(c[0]), "+f"(c[1]), "+f"(c[2]), "+f"(c[3])
        : "r"(a[0]), "r"(a[1]), "r"(a[2]), "r"(a[3]), "r"(b[0]), "r"(b[1]));
}
__device__ __forceinline__ uint32_t packbf(float lo, float hi) {
    uint32_t r;
    asm("cvt.rn.bf16x2.f32 %0, %1, %2;" : "=r"(r) : "f"(hi), "f"(lo));
    return r;
}
__device__ __forceinline__ float bflo(uint32_t r) { return __uint_as_float(r << 16); }
__device__ __forceinline__ float bfhi(uint32_t r) { return __uint_as_float(r & 0xffff0000u); }

// ---------------- fp32 -> bf16 hi/lo split ---------------------------------
__global__ void split_kernel(const float* __restrict__ in,
                             __nv_bfloat16* __restrict__ hi,
                             __nv_bfloat16* __restrict__ lo, int n4) {
    int i = blockIdx.x * blockDim.x + threadIdx.x;
    if (i >= n4) return;
    float4 v = ((const float4*)in)[i];
    float vv[4] = {v.x, v.y, v.z, v.w};
    __nv_bfloat16 h[4], l[4];
#pragma unroll
    for (int j = 0; j < 4; j++) {
        h[j] = __float2bfloat16_rn(vv[j]);
        l[j] = __float2bfloat16_rn(vv[j] - __bfloat162float(h[j]));
    }
    ((__nv_bfloat162*)hi)[2 * i]     = __halves2bfloat162(h[0], h[1]);
    ((__nv_bfloat162*)hi)[2 * i + 1] = __halves2bfloat162(h[2], h[3]);
    ((__nv_bfloat162*)lo)[2 * i]     = __halves2bfloat162(l[0], l[1]);
    ((__nv_bfloat162*)lo)[2 * i + 1] = __halves2bfloat162(l[2], l[3]);
}

// ---------------- RoPE table -------------------------------------------------
__global__ void rope_table_kernel() {
    int idx = blockIdx.x * blockDim.x + threadIdx.x;
    if (idx >= T_ * 64) return;
    int t = idx / 64;
    int i = idx % 64;
    double inv = exp(-((double)i / 64.0) * log(10000.0));
    double ang = (double)t * inv;
    g_cos[idx] = (float)cos(ang);
    g_sin[idx] = (float)sin(ang);
}

// ---------------- RoPE + split + head-major layout ---------------------------
__global__ void rope_split_kernel() {
    int idx = blockIdx.x * blockDim.x + threadIdx.x;
    const int total = B_ * T_ * 24 * 64;
    if (idx >= total) return;
    int i = idx & 63;
    int h = (idx >> 6) % 24;
    int t = ((idx >> 6) / 24) % T_;
    int b = idx / (64 * 24 * T_);
    size_t src = (((size_t)b * T_ + t) * 24 + h) * HD_ + 2 * i;
    float2 v = *(const float2*)&g_qkv[src];
    if (h < NH + NKV) {
        float c = g_cos[t * 64 + i];
        float s = g_sin[t * 64 + i];
        float ox = v.x * c - v.y * s;
        float oy = v.x * s + v.y * c;
        v.x = ox; v.y = oy;
    }
    __nv_bfloat16 hx = __float2bfloat16_rn(v.x);
    __nv_bfloat16 hy = __float2bfloat16_rn(v.y);
    __nv_bfloat16 lx = __float2bfloat16_rn(v.x - __bfloat162float(hx));
    __nv_bfloat16 ly = __float2bfloat16_rn(v.y - __bfloat162float(hy));
    __nv_bfloat16 *dh, *dl;
    size_t off;
    if (h < NH) {
        dh = g_qh; dl = g_ql;
        off = ((size_t)(b * NH + h) * T_ + t) * HD_ + 2 * i;
    } else if (h < NH + NKV) {
        dh = g_kh; dl = g_kl;
        off = ((size_t)(b * NKV + (h - NH)) * T_ + t) * HD_ + 2 * i;
    } else {
        dh = g_vh; dl = g_vl;
        off = ((size_t)(b * NKV + (h - NH - NKV)) * T_ + t) * HD_ + 2 * i;
    }
    *(__nv_bfloat162*)(dh + off) = __halves2bfloat162(hx, hy);
    *(__nv_bfloat162*)(dl + off) = __halves2bfloat162(lx, ly);
}

// ---------------- mma.sync bf16x3 GEMM (NT) — unchanged (validated) ---------
#define GPITCH 40
#define GTILE  (128 * GPITCH)
#define GSTAGE (4 * GTILE)

__global__ __launch_bounds__(256) void gemm_mma(
    const __nv_bfloat16* __restrict__ Ah, const __nv_bfloat16* __restrict__ Al,
    const __nv_bfloat16* __restrict__ Bh, const __nv_bfloat16* __restrict__ Bl,
    float* __restrict__ Cm, int M, int N, int K) {
    extern __shared__ __nv_bfloat16 smg[];
    const int tid = threadIdx.x;
    const int lane = tid & 31;
    const int w = tid >> 5;
    const int wm = w & 1;
    const int wn = w >> 1;
    const size_t bm = (size_t)blockIdx.y * 128;
    const size_t bn = (size_t)blockIdx.x * 128;
    const uint32_t sbase = smem_u32(smg);

    float acc[4][4][4];
#pragma unroll
    for (int i = 0; i < 4; i++)
#pragma unroll
        for (int j = 0; j < 4; j++)
#pragma unroll
            for (int q = 0; q < 4; q++) acc[i][j][q] = 0.0f;

    const int NC = K >> 5;

    auto load_stage = [&](int chunk) {
        uint32_t st = sbase + (uint32_t)(chunk & 1) * (GSTAGE * 2);
        const int k0 = chunk << 5;
#pragma unroll
        for (int s = 0; s < 8; s++) {
            int idx = s * 256 + tid;
            int tile = idx >> 9;
            int row = (idx >> 2) & 127;
            int ch = idx & 3;
            uint32_t dst = st + (uint32_t)(tile * GTILE + row * GPITCH + ch * 8) * 2;
            const __nv_bfloat16* src;
            if (tile == 0)      src = Ah + (bm + row) * (size_t)K + k0 + ch * 8;
            else if (tile == 1) src = Al + (bm + row) * (size_t)K + k0 + ch * 8;
            else if (tile == 2) src = Bh + (bn + row) * (size_t)K + k0 + ch * 8;
            else                src = Bl + (bn + row) * (size_t)K + k0 + ch * 8;
            cpa16(dst, src);
        }
        cpa_commit();
    };

    load_stage(0);

    for (int c = 0; c < NC; c++) {
        if (c + 1 < NC) {
            load_stage(c + 1);
            cpa_wait<1>();
        } else {
            cpa_wait<0>();
        }
        __syncthreads();

        uint32_t st = sbase + (uint32_t)(c & 1) * (GSTAGE * 2);
        uint32_t aHh = st;
        uint32_t aLl = st + (uint32_t)GTILE * 2;
        uint32_t bHh = st + (uint32_t)(2 * GTILE) * 2;
        uint32_t bLl = st + (uint32_t)(3 * GTILE) * 2;

#pragma unroll
        for (int ks = 0; ks < 2; ks++) {
            const int k0 = ks * 16;
            uint32_t ah[4][4], al[4][4];
            {
                int mrow = wm * 64 + (lane & 7) + ((lane >> 3) & 1) * 8;
                int kcol = k0 + (lane >> 4) * 8;
                uint32_t off = (uint32_t)(mrow * GPITCH + kcol) * 2;
#pragma unroll
                for (int mi = 0; mi < 4; mi++) {
                    uint32_t ao = off + (uint32_t)(mi * 16 * GPITCH) * 2;
                    ldsm_x4(ah[mi][0], ah[mi][1], ah[mi][2], ah[mi][3], aHh + ao);
                    ldsm_x4(al[mi][0], al[mi][1], al[mi][2], al[mi][3], aLl + ao);
                }
            }
            uint32_t bh[4][2], bl[4][2];
            {
                int nrow = wn * 32 + (lane & 7);
                int kcol = k0 + ((lane >> 3) & 1) * 8;
                uint32_t off = (uint32_t)(nrow * GPITCH + kcol) * 2;
#pragma unroll
                for (int ni = 0; ni < 4; ni++) {
                    uint32_t bo = off + (uint32_t)(ni * 8 * GPITCH) * 2;
                    ldsm_x2(bh[ni][0], bh[ni][1], bHh + bo);
                    ldsm_x2(bl[ni][0], bl[ni][1], bLl + bo);
                }
            }
#pragma unroll
            for (int mi = 0; mi < 4; mi++)
#pragma unroll
                for (int ni = 0; ni < 4; ni++) {
                    mma_bf16(acc[mi][ni], ah[mi], bh[ni]);
                    mma_bf16(acc[mi][ni], ah[mi], bl[ni]);
                    mma_bf16(acc[mi][ni], al[mi], bh[ni]);
                }
        }
        __syncthreads();
    }

#pragma unroll
    for (int mi = 0; mi < 4; mi++) {
        size_t r0 = bm + wm * 64 + mi * 16 + (lane >> 2);
#pragma unroll
        for (int ni = 0; ni < 4; ni++) {
            size_t col = bn + wn * 32 + ni * 8 + 2 * (lane & 3);
            float2 v0 = make_float2(acc[mi][ni][0], acc[mi][ni][1]);
            float2 v1 = make_float2(acc[mi][ni][2], acc[mi][ni][3]);
            *(float2*)(Cm + r0 * (size_t)N + col) = v0;
            *(float2*)(Cm + (r0 + 8) * (size_t)N + col) = v1;
        }
    }
}

// ---------------- tensor-core flash attention (causal, GQA) ------------------
// CTA: 128 q-rows x (head, batch). 8 warps, each 16 q-rows. KV tile 64.
// smem pitch 136 bf16 (17 x 16B) -> conflict-free ldmatrix, no xor swizzle.
#define FP 136
#define QTILE_E (128 * FP)              // 17408 elems
#define KVTILE_E (64 * FP)              // 8704
#define STAGE_E (4 * KVTILE_E)          // 34816
#define FLASH_SMEM ((2 * QTILE_E + 2 * STAGE_E) * 2)   // 208896 B

__global__ __launch_bounds__(256) void flash_mma() {
    extern __shared__ __nv_bfloat16 fsm[];
    const uint32_t sb = smem_u32(fsm);
    const int tid = threadIdx.x;
    const int lane = tid & 31;
    const int w = tid >> 5;
    const int qt = (int)(gridDim.x - 1 - blockIdx.x);   // longest first
    const int h = blockIdx.y;
    const int b = blockIdx.z;
    const int kvh = h >> 2;
    const int qbase = qt * 128;
    const int nkv = 2 * qt + 2;

    const __nv_bfloat16* qhp = g_qh + ((size_t)(b * NH + h) * T_ + qbase) * HD_;
    const __nv_bfloat16* qlp = g_ql + ((size_t)(b * NH + h) * T_ + qbase) * HD_;
    const __nv_bfloat16* khp = g_kh + (size_t)(b * NKV + kvh) * T_ * HD_;
    const __nv_bfloat16* klp = g_kl + (size_t)(b * NKV + kvh) * T_ * HD_;
    const __nv_bfloat16* vhp = g_vh + (size_t)(b * NKV + kvh) * T_ * HD_;
    const __nv_bfloat16* vlp = g_vl + (size_t)(b * NKV + kvh) * T_ * HD_;

    // Q tile load (hi+lo), grouped with kv stage 0 commit
#pragma unroll
    for (int s = 0; s < 16; s++) {
        int idx = s * 256 + tid;      // 0..4095
        int half = idx >> 11;
        int rem = idx & 2047;
        int row = rem >> 4;
        int ch = rem & 15;
        uint32_t dst = sb + (uint32_t)(half * QTILE_E + row * FP) * 2 + ch * 16;
        const __nv_bfloat16* src = (half ? qlp : qhp) + (size_t)row * HD_ + ch * 8;
        cpa16(dst, src);
    }

    auto load_kv = [&](int ki) {
        int kv0 = ki * 64;
        uint32_t stb = sb + (uint32_t)(2 * QTILE_E + (ki & 1) * STAGE_E) * 2;
#pragma unroll
        for (int s = 0; s < 16; s++) {
            int idx = s * 256 + tid;  // 0..4095
            int tile = idx >> 10;     // 0:Kh 1:Kl 2:Vh 3:Vl
            int rem = idx & 1023;
            int row = rem >> 4;
            int ch = rem & 15;
            uint32_t dst = stb + (uint32_t)(tile * KVTILE_E + row * FP) * 2 + ch * 16;
            const __nv_bfloat16* base =
                (tile == 0) ? khp : (tile == 1) ? klp : (tile == 2) ? vhp : vlp;
            cpa16(dst, base + (size_t)(kv0 + row) * HD_ + ch * 8);
        }
        cpa_commit();
    };

    load_kv(0);   // group 1: Q + kv0
    load_kv(1);   // group 2: kv1

    float O[16][4];
#pragma unroll
    for (int i = 0; i < 16; i++)
#pragma unroll
        for (int c = 0; c < 4; c++) O[i][c] = 0.0f;
    float m_i[2] = {-1e30f, -1e30f};
    float l_i[2] = {0.0f, 0.0f};
    const float scale = 0.08838834764831843f;

    // precomputed lane geometry
    const int mrow = w * 16 + (lane & 7) + ((lane >> 3) & 1) * 8;
    const int kcA = (lane >> 4) * 8;
    const int nrowB = lane & 7;
    const int kcB = ((lane >> 3) & 1) * 8;
    const int krowV = (lane & 7) + ((lane >> 3) & 1) * 8;
    const int ncV = lane >> 4;
    const int row_in_w = lane >> 2;      // 0..7
    const int rowg0 = qbase + w * 16 + row_in_w;

    for (int ki = 0; ki < nkv; ki++) {
        if (ki + 1 < nkv) cpa_wait<1>(); else cpa_wait<0>();
        __syncthreads();

        const bool active = (ki * 64 <= qbase + w * 16 + 15);
        if (active) {
            uint32_t stb = sb + (uint32_t)(2 * QTILE_E + (ki & 1) * STAGE_E) * 2;
            uint32_t kh_b = stb;
            uint32_t kl_b = stb + (uint32_t)KVTILE_E * 2;
            uint32_t vh_b = stb + (uint32_t)(2 * KVTILE_E) * 2;
            uint32_t vl_b = stb + (uint32_t)(3 * KVTILE_E) * 2;

            // ---- S = Q K^T (128x64 per CTA, m16n64 per warp)
            float sacc[8][4];
#pragma unroll
            for (int i = 0; i < 8; i++)
#pragma unroll
                for (int c = 0; c < 4; c++) sacc[i][c] = 0.0f;

#pragma unroll
            for (int ks = 0; ks < 8; ks++) {
                uint32_t ah[4], al[4];
                uint32_t aoff = (uint32_t)(mrow * FP + ks * 16 + kcA) * 2;
                ldsm_x4(ah[0], ah[1], ah[2], ah[3], sb + aoff);
                ldsm_x4(al[0], al[1], al[2], al[3], sb + (uint32_t)QTILE_E * 2 + aoff);
#pragma unroll
                for (int ni = 0; ni < 8; ni++) {
                    uint32_t bh[2], bl[2];
                    uint32_t boff = (uint32_t)((ni * 8 + nrowB) * FP + ks * 16 + kcB) * 2;
                    ldsm_x2(bh[0], bh[1], kh_b + boff);
                    ldsm_x2(bl[0], bl[1], kl_b + boff);
                    mma_bf16(sacc[ni], ah, bh);
                    mma_bf16(sacc[ni], ah, bl);
                    mma_bf16(sacc[ni], al, bh);
                }
            }

            // ---- scale + causal mask
            const int kv0 = ki * 64;
            if (ki >= 2 * qt) {
#pragma unroll
                for (int ni = 0; ni < 8; ni++)
#pragma unroll
                    for (int c = 0; c < 4; c++) {
                        int colg = kv0 + ni * 8 + 2 * (lane & 3) + (c & 1);
                        int rowg = rowg0 + ((c >> 1) << 3);
                        sacc[ni][c] = (colg <= rowg) ? sacc[ni][c] * scale : -1e30f;
                    }
            } else {
#pragma unroll
                for (int ni = 0; ni < 8; ni++)
#pragma unroll
                    for (int c = 0; c < 4; c++) sacc[ni][c] *= scale;
            }

            // ---- online softmax (rows row_in_w, row_in_w+8)
            float mx0 = -1e30f, mx1 = -1e30f;
#pragma unroll
            for (int ni = 0; ni < 8; ni++) {
                mx0 = fmaxf(mx0, fmaxf(sacc[ni][0], sacc[ni][1]));
                mx1 = fmaxf(mx1, fmaxf(sacc[ni][2], sacc[ni][3]));
            }
#pragma unroll
            for (int off = 1; off <= 2; off <<= 1) {
                mx0 = fmaxf(mx0, __shfl_xor_sync(0xffffffffu, mx0, off));
                mx1 = fmaxf(mx1, __shfl_xor_sync(0xffffffffu, mx1, off));
            }
            float mn0 = fmaxf(m_i[0], mx0);
            float mn1 = fmaxf(m_i[1], mx1);
            float cr0 = __expf(m_i[0] - mn0);
            float cr1 = __expf(m_i[1] - mn1);
            m_i[0] = mn0; m_i[1] = mn1;
            float sm0 = 0.0f, sm1 = 0.0f;
#pragma unroll
            for (int ni = 0; ni < 8; ni++) {
                float p0 = __expf(sacc[ni][0] - mn0);
                float p1 = __expf(sacc[ni][1] - mn0);
                float p2 = __expf(sacc[ni][2] - mn1);
                float p3 = __expf(sacc[ni][3] - mn1);
                sacc[ni][0] = p0; sacc[ni][1] = p1;
                sacc[ni][2] = p2; sacc[ni][3] = p3;
                sm0 += p0 + p1;
                sm1 += p2 + p3;
            }
#pragma unroll
            for (int off = 1; off <= 2; off <<= 1) {
                sm0 += __shfl_xor_sync(0xffffffffu, sm0, off);
                sm1 += __shfl_xor_sync(0xffffffffu, sm1, off);
            }
            l_i[0] = l_i[0] * cr0 + sm0;
            l_i[1] = l_i[1] * cr1 + sm1;
#pragma unroll
            for (int ni = 0; ni < 16; ni++) {
                O[ni][0] *= cr0; O[ni][1] *= cr0;
                O[ni][2] *= cr1; O[ni][3] *= cr1;
            }

            // ---- O += P V (m16 x n128, k64)
#pragma unroll
            for (int kt = 0; kt < 4; kt++) {
                uint32_t aP[4], aPl[4];
                {
                    float p0 = sacc[2 * kt][0], p1 = sacc[2 * kt][1];
                    float p2 = sacc[2 * kt][2], p3 = sacc[2 * kt][3];
                    float q0 = sacc[2 * kt + 1][0], q1 = sacc[2 * kt + 1][1];
                    float q2 = sacc[2 * kt + 1][2], q3 = sacc[2 * kt + 1][3];
                    aP[0] = packbf(p0, p1);
                    aP[1] = packbf(p2, p3);
                    aP[2] = packbf(q0, q1);
                    aP[3] = packbf(q2, q3);
                    aPl[0] = packbf(p0 - bflo(aP[0]), p1 - bfhi(aP[0]));
                    aPl[1] = packbf(p2 - bflo(aP[1]), p3 - bfhi(aP[1]));
                    aPl[2] = packbf(q0 - bflo(aP[2]), q1 - bfhi(aP[2]));
                    aPl[3] = packbf(q2 - bflo(aP[3]), q3 - bfhi(aP[3]));
                }
#pragma unroll
                for (int njp = 0; njp < 8; njp++) {
                    uint32_t bh[4], bl[4];
                    uint32_t voff =
                        (uint32_t)((kt * 16 + krowV) * FP + (2 * njp + ncV) * 8) * 2;
                    ldsm_x4_t(bh[0], bh[1], bh[2], bh[3], vh_b + voff);
                    ldsm_x4_t(bl[0], bl[1], bl[2], bl[3], vl_b + voff);
                    mma_bf16(O[2 * njp], aP, bh);
                    mma_bf16(O[2 * njp], aP, bl);
                    mma_bf16(O[2 * njp], aPl, bh);
                    mma_bf16(O[2 * njp + 1], aP, bh + 2);
                    mma_bf16(O[2 * njp + 1], aP, bl + 2);
                    mma_bf16(O[2 * njp + 1], aPl, bh + 2);
                }
            }
        }
        __syncthreads();
        if (ki + 2 < nkv) load_kv(ki + 2);
    }

    // ---- epilogue: O / l -> g_y
    float inv0 = 1.0f / l_i[0];
    float inv1 = 1.0f / l_i[1];
    const int rg0 = qbase + w * 16 + row_in_w;
#pragma unroll
    for (int ni = 0; ni < 16; ni++) {
        int col = h * HD_ + ni * 8 + 2 * (lane & 3);
        float* y0 = g_y + ((size_t)b * T_ + rg0) * C_ + col;
        float* y1 = g_y + ((size_t)b * T_ + rg0 + 8) * C_ + col;
        *(float2*)y0 = make_float2(O[ni][0] * inv0, O[ni][1] * inv0);
        *(float2*)y1 = make_float2(O[ni][2] * inv1, O[ni][3] * inv1);
    }
}

// ---------------- driver ----------------------------------------------------
extern "C" void kernel_launch(void* const* d_in, const int* in_sizes, int n_in,
                              void* d_out, int out_size) {
    const float* x = nullptr;
    const float* w_attn = nullptr;
    const float* w_proj = nullptr;
    for (int i = 0; i < n_in; i++) {
        if (in_sizes[i] == B_ * T_ * C_) x = (const float*)d_in[i];
        else if (in_sizes[i] == QKVD * C_) w_attn = (const float*)d_in[i];
        else if (in_sizes[i] == C_ * C_) w_proj = (const float*)d_in[i];
    }
    float* out = (float*)d_out;

    float *qkv, *y;
    __nv_bfloat16 *xh, *xl, *yh, *yl, *wah, *wal, *wph, *wpl;
    cudaGetSymbolAddress((void**)&qkv, g_qkv);
    cudaGetSymbolAddress((void**)&y, g_y);
    cudaGetSymbolAddress((void**)&xh, g_xh);
    cudaGetSymbolAddress((void**)&xl, g_xl);
    cudaGetSymbolAddress((void**)&yh, g_yh);
    cudaGetSymbolAddress((void**)&yl, g_yl);
    cudaGetSymbolAddress((void**)&wah, g_wah);
    cudaGetSymbolAddress((void**)&wal, g_wal);
    cudaGetSymbolAddress((void**)&wph, g_wph);
    cudaGetSymbolAddress((void**)&wpl, g_wpl);

    const int gemm_smem = 2 * GSTAGE * 2;
    cudaFuncSetAttribute(gemm_mma, cudaFuncAttributeMaxDynamicSharedMemorySize,
                         gemm_smem);
    cudaFuncSetAttribute(flash_mma, cudaFuncAttributeMaxDynamicSharedMemorySize,
                         FLASH_SMEM);

    // RoPE table
    rope_table_kernel<<<(T_ * 64 + 255) / 256, 256>>>();

    // splits: x, w_attn, w_proj
    {
        int n4 = (B_ * T_ * C_) / 4;
        split_kernel<<<(n4 + 255) / 256, 256>>>(x, xh, xl, n4);
        n4 = (QKVD * C_) / 4;
        split_kernel<<<(n4 + 255) / 256, 256>>>(w_attn, wah, wal, n4);
        n4 = (C_ * C_) / 4;
        split_kernel<<<(n4 + 255) / 256, 256>>>(w_proj, wph, wpl, n4);
    }

    // GEMM1: qkv = x @ w_attn^T
    {
        dim3 grid(QKVD / 128, (B_ * T_) / 128);
        gemm_mma<<<grid, 256, gemm_smem>>>(xh, xl, wah, wal, qkv,
                                           B_ * T_, QKVD, C_);
    }

    // RoPE + split + head-major layout for q/k/v
    {
        int total = B_ * T_ * 24 * 64;
        rope_split_kernel<<<(total + 255) / 256, 256>>>();
    }

    // tensor-core flash attention -> y
    {
        dim3 grid(T_ / 128, NH, B_);
        flash_mma<<<grid, 256, FLASH_SMEM>>>();
    }

    // split y, then GEMM2: out = y @ w_proj^T
    {
        int n4 = (B_ * T_ * C_) / 4;
        split_kernel<<<(n4 + 255) / 256, 256>>>(y, yh, yl, n4);
        dim3 grid(C_ / 128, (B_ * T_) / 128);
        gemm_mma<<<grid, 256, gemm_smem>>>(yh, yl, wph, wpl, out,
                                           B_ * T_, C_, C_);
    }
}